// round 6
// baseline (speedup 1.0000x reference)
#include <cuda_runtime.h>
#include <cstdint>

#define N_SRC   100000
#define N_TGT   50000
#define N_EDGES 600000
#define CH      128
#define NREL    7
#define NTYP    4
#define NSEG    11
#define NCHUNK  44          // NSEG * (128/32)

// GEMM tiling
#define TILE_M  64
#define SSTR    36                      // padded row stride (words)
#define A_WORDS (TILE_M * SSTR)         // 2304
#define B_WORDS (128 * SSTR)            // 4608
#define STAGE_WORDS (A_WORDS + B_WORDS) // 6912
#define NSTAGE  4
#define GSMEM_BYTES (NSTAGE * STAGE_WORDS * 4)   // 110592

// Scratch (allocation-free rule: __device__ globals)
__device__ float    g_agg[(size_t)N_TGT * NREL * CH];   // pre-normalized sums
__device__ float    g_cnt[N_TGT * NREL];
__device__ uint32_t g_wtf32[NSEG * CH * CH];            // tf32 weights, seg-major

__device__ __forceinline__ uint32_t to_tf32(float x) {
    uint32_t r;
    asm("cvt.rna.tf32.f32 %0, %1;" : "=r"(r) : "f"(x));
    return r;
}
__device__ __forceinline__ uint32_t smem_u32(const void* p) {
    uint32_t a;
    asm("{ .reg .u64 t; cvta.to.shared.u64 t, %1; cvt.u32.u64 %0, t; }" : "=r"(a) : "l"(p));
    return a;
}
__device__ __forceinline__ void cp16(uint32_t dst, const void* src, bool pred) {
    asm volatile("cp.async.ca.shared.global [%0], [%1], 16, %2;"
                 :: "r"(dst), "l"(src), "r"(pred ? 16 : 0) : "memory");
}
#define CP_COMMIT() asm volatile("cp.async.commit_group;" ::: "memory")
#define CP_WAIT(n)  asm volatile("cp.async.wait_group %0;" :: "n"(n) : "memory")

__device__ __forceinline__ void mma_tf32(float* c,
    uint32_t a0, uint32_t a1, uint32_t a2, uint32_t a3,
    uint32_t b0, uint32_t b1)
{
    asm volatile(
        "mma.sync.aligned.m16n8k8.row.col.f32.tf32.tf32.f32 "
        "{%0,%1,%2,%3}, {%4,%5,%6,%7}, {%8,%9}, {%0,%1,%2,%3};"
        : "+f"(c[0]), "+f"(c[1]), "+f"(c[2]), "+f"(c[3])
        : "r"(a0), "r"(a1), "r"(a2), "r"(a3), "r"(b0), "r"(b1));
}

// ---------------- kernel 0: weight pre-convert ----------------
__global__ __launch_bounds__(256) void prep_weights(
    const float* __restrict__ relw, const float* __restrict__ rootw,
    uint32_t* __restrict__ wt)
{
    int i = blockIdx.x * 256 + threadIdx.x;
    const int NREL4 = NREL * CH * CH / 4;
    const int TOT4  = NSEG * CH * CH / 4;
    if (i >= TOT4) return;
    float4 v = (i < NREL4) ? ((const float4*)relw)[i]
                           : ((const float4*)rootw)[i - NREL4];
    uint4 w;
    w.x = to_tf32(v.x); w.y = to_tf32(v.y);
    w.z = to_tf32(v.z); w.w = to_tf32(v.w);
    ((uint4*)wt)[i] = w;
}

// ---------------- kernel 1: edge degree count ----------------
__global__ __launch_bounds__(256) void count_kernel(
    const int* __restrict__ edst, const int* __restrict__ etyp,
    float* __restrict__ cnt)
{
    int e = blockIdx.x * 256 + threadIdx.x;
    if (e >= N_EDGES) return;
    int d = __ldg(edst + e);
    int t = __ldg(etyp + e);
    asm volatile("red.global.add.f32 [%0], %1;"
                 :: "l"(cnt + d * NREL + t), "f"(1.0f) : "memory");
}

// ---------------- kernel 2: normalized edge scatter ----------------
__global__ __launch_bounds__(256) void scatter_kernel(
    const float* __restrict__ xs,
    const int* __restrict__ esrc, const int* __restrict__ edst,
    const int* __restrict__ etyp, const float* __restrict__ cnt,
    float* __restrict__ agg)
{
    int w = (blockIdx.x * 256 + threadIdx.x) >> 5;
    int lane = threadIdx.x & 31;
    if (w >= N_EDGES) return;
    int s = __ldg(esrc + w);
    int d = __ldg(edst + w);
    int t = __ldg(etyp + w);
    float inv = 1.0f / fmaxf(__ldg(cnt + d * NREL + t), 1.0f);
    float4 v = ((const float4*)(xs + ((size_t)s << 7)))[lane];
    v.x *= inv; v.y *= inv; v.z *= inv; v.w *= inv;
    float* base = agg + (((size_t)d * NREL + t) << 7) + (lane << 2);
    asm volatile("red.global.add.v4.f32 [%0], {%1,%2,%3,%4};"
                 :: "l"(base), "f"(v.x), "f"(v.y), "f"(v.z), "f"(v.w) : "memory");
}

// ---------------- kernel 3: pipelined tf32 GEMM ----------------
// 4-stage cp.async, single barrier/chunk, register double-buffered fragments.
__global__ __launch_bounds__(256, 2) void gemm_mma_kernel(
    const float* __restrict__ agg, const uint32_t* __restrict__ wt,
    const float* __restrict__ xt, const float* __restrict__ rootb,
    const int* __restrict__ ttype, float* __restrict__ out)
{
    extern __shared__ uint32_t smw[];
    __shared__ int sTyp[TILE_M];

    const int tid = threadIdx.x;
    const int wid = tid >> 5;
    const int lid = tid & 31;
    const int wm = wid & 1;        // 32-row half
    const int wn = wid >> 1;       // 32-col quarter
    const int row0 = blockIdx.x * TILE_M;
    const uint32_t sb = smem_u32(smw);

    if (tid < TILE_M) {
        int g = row0 + tid;
        sTyp[tid] = (g < N_TGT) ? ttype[g] : -1;
    }
    __syncthreads();

    auto issue_chunk = [&](int ci, int stage) {
        int seg = ci >> 2;
        int k0  = (ci & 3) << 5;
        uint32_t aB = sb + stage * (STAGE_WORDS * 4);
        uint32_t bB = aB + A_WORDS * 4;
#pragma unroll
        for (int j = 0; j < 2; ++j) {
            int i = tid + (j << 8);            // 0..511
            int row = i >> 3, kv = i & 7;
            int g = row0 + row;
            bool ok = (g < N_TGT);
            int gc = ok ? g : 0;
            const float* src;
            if (seg < NREL) {
                src = agg + (((size_t)gc * NREL + seg) << 7) + k0 + (kv << 2);
            } else {
                ok = ok && (sTyp[row] == seg - NREL);
                src = xt + ((size_t)gc << 7) + k0 + (kv << 2);
            }
            cp16(aB + row * (SSTR * 4) + (kv << 4), src, ok);
        }
        const uint32_t* wsrc = wt + ((size_t)seg << 14) + k0;
#pragma unroll
        for (int j = 0; j < 4; ++j) {
            int i = tid + (j << 8);            // 0..1023
            int c = i >> 3, kv = i & 7;
            cp16(bB + c * (SSTR * 4) + (kv << 4), wsrc + (c << 7) + (kv << 2), true);
        }
    };

    float acc[2][4][4];
#pragma unroll
    for (int mi = 0; mi < 2; ++mi)
#pragma unroll
        for (int ni = 0; ni < 4; ++ni)
#pragma unroll
            for (int q = 0; q < 4; ++q) acc[mi][ni][q] = 0.0f;

    // prologue: fill 3 of 4 stages
#pragma unroll
    for (int p = 0; p < NSTAGE - 1; ++p) { issue_chunk(p, p); CP_COMMIT(); }

    const int arow  = (wm << 5) + (lid >> 2);
    const int bcol0 = (wn << 5) + (lid >> 2);
    const int klo   = lid & 3;

    uint32_t fa[2][2][4];   // [buf][mi][frag]
    uint32_t fb[2][4][2];   // [buf][ni][frag]

    for (int ci = 0; ci < NCHUNK; ++ci) {
        int stage = ci & (NSTAGE - 1);
        CP_WAIT(2);                    // chunk ci arrived (this thread)
        __syncthreads();               // visible to all; compute ci-1 done by all
        // refill the stage consumed at ci-1 with chunk ci+3
        if (ci + NSTAGE - 1 < NCHUNK)
            issue_chunk(ci + NSTAGE - 1, (ci + NSTAGE - 1) & (NSTAGE - 1));
        CP_COMMIT();

        const uint32_t* sw = smw + stage * STAGE_WORDS;
        const uint32_t* pA = sw + arow * SSTR;
        const uint32_t* pB = sw + A_WORDS + bcol0 * SSTR;

        // load fragments for ks=0
        {
            int kk = klo;
#pragma unroll
            for (int ni = 0; ni < 4; ++ni) {
                fb[0][ni][0] = pB[(ni << 3) * SSTR + kk];
                fb[0][ni][1] = pB[(ni << 3) * SSTR + kk + 4];
            }
#pragma unroll
            for (int mi = 0; mi < 2; ++mi) {
                fa[0][mi][0] = pA[(mi << 4) * SSTR + kk];
                fa[0][mi][1] = pA[((mi << 4) + 8) * SSTR + kk];
                fa[0][mi][2] = pA[(mi << 4) * SSTR + kk + 4];
                fa[0][mi][3] = pA[((mi << 4) + 8) * SSTR + kk + 4];
            }
        }
#pragma unroll
        for (int ks = 0; ks < 4; ++ks) {
            int cur = ks & 1, nxt = cur ^ 1;
            if (ks < 3) {              // prefetch ks+1 fragments (overlaps MMA)
                int kk = ((ks + 1) << 3) + klo;
#pragma unroll
                for (int ni = 0; ni < 4; ++ni) {
                    fb[nxt][ni][0] = pB[(ni << 3) * SSTR + kk];
                    fb[nxt][ni][1] = pB[(ni << 3) * SSTR + kk + 4];
                }
#pragma unroll
                for (int mi = 0; mi < 2; ++mi) {
                    fa[nxt][mi][0] = pA[(mi << 4) * SSTR + kk];
                    fa[nxt][mi][1] = pA[((mi << 4) + 8) * SSTR + kk];
                    fa[nxt][mi][2] = pA[(mi << 4) * SSTR + kk + 4];
                    fa[nxt][mi][3] = pA[((mi << 4) + 8) * SSTR + kk + 4];
                }
            }
#pragma unroll
            for (int mi = 0; mi < 2; ++mi)
#pragma unroll
                for (int ni = 0; ni < 4; ++ni)
                    mma_tf32(acc[mi][ni],
                             fa[cur][mi][0], fa[cur][mi][1],
                             fa[cur][mi][2], fa[cur][mi][3],
                             fb[cur][ni][0], fb[cur][ni][1]);
        }
    }

    // ---- epilogue: bias + store ----
#pragma unroll
    for (int mi = 0; mi < 2; ++mi) {
#pragma unroll
        for (int half = 0; half < 2; ++half) {
            int row = (wm << 5) + (mi << 4) + (half << 3) + (lid >> 2);
            int g = row0 + row;
            if (g >= N_TGT) continue;
            int t = sTyp[row];
#pragma unroll
            for (int ni = 0; ni < 4; ++ni) {
                int col = (wn << 5) + (ni << 3) + ((lid & 3) << 1);
                float2 o;
                o.x = acc[mi][ni][half * 2 + 0] + rootb[(t << 7) + col];
                o.y = acc[mi][ni][half * 2 + 1] + rootb[(t << 7) + col + 1];
                *(float2*)(out + ((size_t)g << 7) + col) = o;
            }
        }
    }
}

extern "C" void kernel_launch(void* const* d_in, const int* in_sizes, int n_in,
                              void* d_out, int out_size)
{
    const float* x_src  = (const float*)d_in[0];
    const float* x_tgt  = (const float*)d_in[1];
    const float* rel_w  = (const float*)d_in[2];
    const float* root_w = (const float*)d_in[3];
    const float* root_b = (const float*)d_in[4];
    const int*   e_src  = (const int*)d_in[5];
    const int*   e_dst  = (const int*)d_in[6];
    const int*   e_typ  = (const int*)d_in[7];
    const int*   n_typ  = (const int*)d_in[8];
    float* out = (float*)d_out;

    void *aggp = nullptr, *cntp = nullptr, *wtp = nullptr;
    cudaGetSymbolAddress(&aggp, g_agg);
    cudaGetSymbolAddress(&cntp, g_cnt);
    cudaGetSymbolAddress(&wtp,  g_wtf32);
    cudaMemsetAsync(aggp, 0, (size_t)N_TGT * NREL * CH * sizeof(float));
    cudaMemsetAsync(cntp, 0, (size_t)N_TGT * NREL * sizeof(float));

    prep_weights<<<(NSEG * CH * CH / 4 + 255) / 256, 256>>>(rel_w, root_w, (uint32_t*)wtp);
    count_kernel<<<(N_EDGES + 255) / 256, 256>>>(e_dst, e_typ, (float*)cntp);
    scatter_kernel<<<N_EDGES / 8, 256>>>(x_src, e_src, e_dst, e_typ,
                                         (const float*)cntp, (float*)aggp);

    cudaFuncSetAttribute(gemm_mma_kernel,
                         cudaFuncAttributeMaxDynamicSharedMemorySize, GSMEM_BYTES);
    gemm_mma_kernel<<<(N_TGT + TILE_M - 1) / TILE_M, 256, GSMEM_BYTES>>>(
        (const float*)aggp, (const uint32_t*)wtp, x_tgt, root_b, n_typ, out);
}

// round 7
// speedup vs baseline: 1.2196x; 1.2196x over previous
#include <cuda_runtime.h>
#include <cstdint>

#define N_SRC   100000
#define N_TGT   50000
#define N_EDGES 600000
#define CH      128
#define NREL    7
#define NTYP    4
#define NSEG    11
#define NCHUNK  44          // NSEG * (128/32)

// GEMM tiling
#define TILE_M  64
#define SSTR    36                      // padded row stride (words)
#define A_WORDS (TILE_M * SSTR)         // 2304
#define B_WORDS (128 * SSTR)            // 4608
#define STAGE_WORDS (A_WORDS + B_WORDS) // 6912
#define STAGE_BYTES (STAGE_WORDS * 4)   // 27648
#define NSTAGE  3
#define GSMEM_BYTES (NSTAGE * STAGE_BYTES)   // 82944

// Scratch (allocation-free rule: __device__ globals)
__device__ float    g_agg[(size_t)N_TGT * NREL * CH];   // pre-normalized sums
__device__ float    g_cnt[N_TGT * NREL];
__device__ uint32_t g_wtf32[NSEG * CH * CH];            // tf32 weights, seg-major

__device__ __forceinline__ uint32_t to_tf32(float x) {
    uint32_t r;
    asm("cvt.rna.tf32.f32 %0, %1;" : "=r"(r) : "f"(x));
    return r;
}
__device__ __forceinline__ uint32_t smem_u32(const void* p) {
    uint32_t a;
    asm("{ .reg .u64 t; cvta.to.shared.u64 t, %1; cvt.u32.u64 %0, t; }" : "=r"(a) : "l"(p));
    return a;
}
__device__ __forceinline__ void cp16(uint32_t dst, const void* src, bool pred) {
    asm volatile("cp.async.ca.shared.global [%0], [%1], 16, %2;"
                 :: "r"(dst), "l"(src), "r"(pred ? 16 : 0) : "memory");
}
#define CP_COMMIT() asm volatile("cp.async.commit_group;" ::: "memory")
#define CP_WAIT(n)  asm volatile("cp.async.wait_group %0;" :: "n"(n) : "memory")

#define LDSM_X4(r0, r1, r2, r3, addr) \
    asm volatile("ldmatrix.sync.aligned.m8n8.x4.shared.b16 {%0,%1,%2,%3}, [%4];" \
        : "=r"(r0), "=r"(r1), "=r"(r2), "=r"(r3) : "r"(addr))

__device__ __forceinline__ void mma_tf32(float* c,
    uint32_t a0, uint32_t a1, uint32_t a2, uint32_t a3,
    uint32_t b0, uint32_t b1)
{
    asm volatile(
        "mma.sync.aligned.m16n8k8.row.col.f32.tf32.tf32.f32 "
        "{%0,%1,%2,%3}, {%4,%5,%6,%7}, {%8,%9}, {%0,%1,%2,%3};"
        : "+f"(c[0]), "+f"(c[1]), "+f"(c[2]), "+f"(c[3])
        : "r"(a0), "r"(a1), "r"(a2), "r"(a3), "r"(b0), "r"(b1));
}

// ---------------- kernel 0: weight pre-convert ----------------
__global__ __launch_bounds__(256) void prep_weights(
    const float* __restrict__ relw, const float* __restrict__ rootw,
    uint32_t* __restrict__ wt)
{
    int i = blockIdx.x * 256 + threadIdx.x;
    const int NREL4 = NREL * CH * CH / 4;
    const int TOT4  = NSEG * CH * CH / 4;
    if (i >= TOT4) return;
    float4 v = (i < NREL4) ? ((const float4*)relw)[i]
                           : ((const float4*)rootw)[i - NREL4];
    uint4 w;
    w.x = to_tf32(v.x); w.y = to_tf32(v.y);
    w.z = to_tf32(v.z); w.w = to_tf32(v.w);
    ((uint4*)wt)[i] = w;
}

// ---------------- kernel 1: edge degree count ----------------
__global__ __launch_bounds__(256) void count_kernel(
    const int* __restrict__ edst, const int* __restrict__ etyp,
    float* __restrict__ cnt)
{
    int e = blockIdx.x * 256 + threadIdx.x;
    if (e >= N_EDGES) return;
    int d = __ldg(edst + e);
    int t = __ldg(etyp + e);
    asm volatile("red.global.add.f32 [%0], %1;"
                 :: "l"(cnt + d * NREL + t), "f"(1.0f) : "memory");
}

// ---------------- kernel 2: normalized edge scatter ----------------
__global__ __launch_bounds__(256) void scatter_kernel(
    const float* __restrict__ xs,
    const int* __restrict__ esrc, const int* __restrict__ edst,
    const int* __restrict__ etyp, const float* __restrict__ cnt,
    float* __restrict__ agg)
{
    int w = (blockIdx.x * 256 + threadIdx.x) >> 5;
    int lane = threadIdx.x & 31;
    if (w >= N_EDGES) return;
    int s = __ldg(esrc + w);
    int d = __ldg(edst + w);
    int t = __ldg(etyp + w);
    float inv = 1.0f / fmaxf(__ldg(cnt + d * NREL + t), 1.0f);
    float4 v = ((const float4*)(xs + ((size_t)s << 7)))[lane];
    v.x *= inv; v.y *= inv; v.z *= inv; v.w *= inv;
    float* base = agg + (((size_t)d * NREL + t) << 7) + (lane << 2);
    asm volatile("red.global.add.v4.f32 [%0], {%1,%2,%3,%4};"
                 :: "l"(base), "f"(v.x), "f"(v.y), "f"(v.z), "f"(v.w) : "memory");
}

// ---------------- kernel 3: pipelined tf32 GEMM (ldmatrix fragments) ------
// R5 loop skeleton (3-stage cp.async, two barriers/chunk) + LDSM fragment
// loads: 4 ldmatrix.x4 per thread per ks instead of 16 scalar LDS.
__global__ __launch_bounds__(256, 2) void gemm_mma_kernel(
    const float* __restrict__ agg, const uint32_t* __restrict__ wt,
    const float* __restrict__ xt, const float* __restrict__ rootb,
    const int* __restrict__ ttype, float* __restrict__ out)
{
    extern __shared__ uint32_t smw[];
    __shared__ int sTyp[TILE_M];

    const int tid = threadIdx.x;
    const int wid = tid >> 5;
    const int lid = tid & 31;
    const int wm = wid & 1;        // 32-row half
    const int wn = wid >> 1;       // 32-col quarter
    const int row0 = blockIdx.x * TILE_M;
    const uint32_t sb = smem_u32(smw);

    if (tid < TILE_M) {
        int g = row0 + tid;
        sTyp[tid] = (g < N_TGT) ? ttype[g] : -1;
    }
    __syncthreads();

    auto issue_chunk = [&](int ci, int stage) {
        int seg = ci >> 2;
        int k0  = (ci & 3) << 5;
        uint32_t aB = sb + stage * STAGE_BYTES;
        uint32_t bB = aB + A_WORDS * 4;
#pragma unroll
        for (int j = 0; j < 2; ++j) {
            int i = tid + (j << 8);            // 0..511
            int row = i >> 3, kv = i & 7;
            int g = row0 + row;
            bool ok = (g < N_TGT);
            int gc = ok ? g : 0;
            const float* src;
            if (seg < NREL) {
                src = agg + (((size_t)gc * NREL + seg) << 7) + k0 + (kv << 2);
            } else {
                ok = ok && (sTyp[row] == seg - NREL);
                src = xt + ((size_t)gc << 7) + k0 + (kv << 2);
            }
            cp16(aB + row * (SSTR * 4) + (kv << 4), src, ok);
        }
        const uint32_t* wsrc = wt + ((size_t)seg << 14) + k0;
#pragma unroll
        for (int j = 0; j < 4; ++j) {
            int i = tid + (j << 8);            // 0..1023
            int c = i >> 3, kv = i & 7;
            cp16(bB + c * (SSTR * 4) + (kv << 4), wsrc + (c << 7) + (kv << 2), true);
        }
    };

    float acc[2][4][4];
#pragma unroll
    for (int mi = 0; mi < 2; ++mi)
#pragma unroll
        for (int ni = 0; ni < 4; ++ni)
#pragma unroll
            for (int q = 0; q < 4; ++q) acc[mi][ni][q] = 0.0f;

    // prologue: fill all 3 stages
#pragma unroll
    for (int p = 0; p < NSTAGE; ++p) { issue_chunk(p, p); CP_COMMIT(); }

    // ldmatrix per-lane byte offsets (see mapping proof in commit message):
    // A x4: lanes {0-7: r0-7 k0-3, 8-15: r8-15 k0-3, 16-23: r0-7 k4-7, 24-31: r8-15 k4-7}
    const uint32_t laneA = (uint32_t)(((wm << 5) + (lid & 15)) * (SSTR * 4)
                                      + ((lid >> 4) << 4));
    // B x4: lanes {0-7: n0-7 k0-3, 8-15: n0-7 k4-7, 16-23: n8-15 k0-3, 24-31: n8-15 k4-7}
    const uint32_t laneB = (uint32_t)((((wn << 5) + ((lid >> 4) << 3) + (lid & 7)) * (SSTR * 4))
                                      + (((lid >> 3) & 1) << 4));
    const uint32_t MI_OFF = 16u * SSTR * 4;   // 16 rows
    const uint32_t NI_OFF = 16u * SSTR * 4;   // 16 cols

    for (int ci = 0; ci < NCHUNK; ++ci) {
        int stage = ci % NSTAGE;
        CP_WAIT(NSTAGE - 1);           // chunk ci arrived (this thread)
        __syncthreads();               // ...and for all threads
        const uint32_t aA = sb + stage * STAGE_BYTES + laneA;
        const uint32_t bA = sb + stage * STAGE_BYTES + A_WORDS * 4 + laneB;
#pragma unroll
        for (int ks = 0; ks < 4; ++ks) {
            const uint32_t ko = (uint32_t)(ks << 5);   // 8 k-words = 32 bytes
            uint32_t a0[4], a1[4], b01[4], b23[4];
            LDSM_X4(a0[0], a0[1], a0[2], a0[3], aA + ko);
            LDSM_X4(a1[0], a1[1], a1[2], a1[3], aA + MI_OFF + ko);
            LDSM_X4(b01[0], b01[1], b01[2], b01[3], bA + ko);
            LDSM_X4(b23[0], b23[1], b23[2], b23[3], bA + NI_OFF + ko);
            mma_tf32(acc[0][0], a0[0], a0[1], a0[2], a0[3], b01[0], b01[1]);
            mma_tf32(acc[0][1], a0[0], a0[1], a0[2], a0[3], b01[2], b01[3]);
            mma_tf32(acc[0][2], a0[0], a0[1], a0[2], a0[3], b23[0], b23[1]);
            mma_tf32(acc[0][3], a0[0], a0[1], a0[2], a0[3], b23[2], b23[3]);
            mma_tf32(acc[1][0], a1[0], a1[1], a1[2], a1[3], b01[0], b01[1]);
            mma_tf32(acc[1][1], a1[0], a1[1], a1[2], a1[3], b01[2], b01[3]);
            mma_tf32(acc[1][2], a1[0], a1[1], a1[2], a1[3], b23[0], b23[1]);
            mma_tf32(acc[1][3], a1[0], a1[1], a1[2], a1[3], b23[2], b23[3]);
        }
        __syncthreads();               // all warps done with this stage
        if (ci + NSTAGE < NCHUNK) issue_chunk(ci + NSTAGE, stage);
        CP_COMMIT();                   // keep group accounting uniform
    }

    // ---- epilogue: bias + store ----
#pragma unroll
    for (int mi = 0; mi < 2; ++mi) {
#pragma unroll
        for (int half = 0; half < 2; ++half) {
            int row = (wm << 5) + (mi << 4) + (half << 3) + (lid >> 2);
            int g = row0 + row;
            if (g >= N_TGT) continue;
            int t = sTyp[row];
#pragma unroll
            for (int ni = 0; ni < 4; ++ni) {
                int col = (wn << 5) + (ni << 3) + ((lid & 3) << 1);
                float2 o;
                o.x = acc[mi][ni][half * 2 + 0] + rootb[(t << 7) + col];
                o.y = acc[mi][ni][half * 2 + 1] + rootb[(t << 7) + col + 1];
                *(float2*)(out + ((size_t)g << 7) + col) = o;
            }
        }
    }
}

extern "C" void kernel_launch(void* const* d_in, const int* in_sizes, int n_in,
                              void* d_out, int out_size)
{
    const float* x_src  = (const float*)d_in[0];
    const float* x_tgt  = (const float*)d_in[1];
    const float* rel_w  = (const float*)d_in[2];
    const float* root_w = (const float*)d_in[3];
    const float* root_b = (const float*)d_in[4];
    const int*   e_src  = (const int*)d_in[5];
    const int*   e_dst  = (const int*)d_in[6];
    const int*   e_typ  = (const int*)d_in[7];
    const int*   n_typ  = (const int*)d_in[8];
    float* out = (float*)d_out;

    void *aggp = nullptr, *cntp = nullptr, *wtp = nullptr;
    cudaGetSymbolAddress(&aggp, g_agg);
    cudaGetSymbolAddress(&cntp, g_cnt);
    cudaGetSymbolAddress(&wtp,  g_wtf32);
    cudaMemsetAsync(aggp, 0, (size_t)N_TGT * NREL * CH * sizeof(float));
    cudaMemsetAsync(cntp, 0, (size_t)N_TGT * NREL * sizeof(float));

    prep_weights<<<(NSEG * CH * CH / 4 + 255) / 256, 256>>>(rel_w, root_w, (uint32_t*)wtp);
    count_kernel<<<(N_EDGES + 255) / 256, 256>>>(e_dst, e_typ, (float*)cntp);
    scatter_kernel<<<N_EDGES / 8, 256>>>(x_src, e_src, e_dst, e_typ,
                                         (const float*)cntp, (float*)aggp);

    cudaFuncSetAttribute(gemm_mma_kernel,
                         cudaFuncAttributeMaxDynamicSharedMemorySize, GSMEM_BYTES);
    gemm_mma_kernel<<<(N_TGT + TILE_M - 1) / TILE_M, 256, GSMEM_BYTES>>>(
        (const float*)aggp, (const uint32_t*)wtp, x_tgt, root_b, n_typ, out);
}